// round 14
// baseline (speedup 1.0000x reference)
#include <cuda_runtime.h>

#define EPS      1e-4f
#define FRAMES   4000
#define THREADS  256
#define TILE     (THREADS * 4)        // 1024 elements per tile
#define NTILES   4                    // 4 * 1024 = 4096 >= 4000
#define NWARPS   (THREADS / 32)       // 8
#define GRID     456                  // ~3 CTAs/SM on 152 SMs, persistent

__global__ __launch_bounds__(THREADS)
void cumnorm_kernel(const float* __restrict__ x, float* __restrict__ out, int nrows)
{
    __shared__ float2 wsum[NTILES * NWARPS];

    const int tid  = threadIdx.x;
    const int lane = tid & 31;
    const int warp = tid >> 5;

    int r = blockIdx.x;
    if (r >= nrows) return;

    // ---- prime the pipeline: load first row ----
    float4 vn[NTILES];
    {
        const float* xr = x + (size_t)r * FRAMES;
        #pragma unroll
        for (int k = 0; k < NTILES; ++k) {
            const int e = k * TILE + 4 * tid;
            vn[k] = (k < NTILES - 1 || e < FRAMES)
                    ? *reinterpret_cast<const float4*>(xr + e)
                    : make_float4(0.f, 0.f, 0.f, 0.f);
        }
    }

    bool first = true;
    for (; r < nrows; r += GRID) {
        // take ownership of the prefetched row
        float4 v[NTILES];
        #pragma unroll
        for (int k = 0; k < NTILES; ++k) v[k] = vn[k];

        // ---- issue next row's loads NOW (fly under scan+tail) ----
        const int rn = r + GRID;
        if (rn < nrows) {
            const float* xr = x + (size_t)rn * FRAMES;
            #pragma unroll
            for (int k = 0; k < NTILES; ++k) {
                const int e = k * TILE + 4 * tid;
                if (k < NTILES - 1 || e < FRAMES)
                    vn[k] = *reinterpret_cast<const float4*>(xr + e);
            }
        }

        // ---- per-tile thread totals ----
        float is[NTILES], iq[NTILES];
        #pragma unroll
        for (int k = 0; k < NTILES; ++k) {
            const float4 vk = v[k];
            is[k] = (vk.x + vk.y) + (vk.z + vk.w);
            float q = vk.x * vk.x;
            q = fmaf(vk.y, vk.y, q);
            q = fmaf(vk.z, vk.z, q);
            iq[k] = fmaf(vk.w, vk.w, q);
        }

        // ---- 4 warp scans interleaved ----
        #pragma unroll
        for (int d = 1; d < 32; d <<= 1) {
            #pragma unroll
            for (int k = 0; k < NTILES; ++k) {
                float as = __shfl_up_sync(0xffffffffu, is[k], d);
                float aq = __shfl_up_sync(0xffffffffu, iq[k], d);
                if (lane >= d) { is[k] += as; iq[k] += aq; }
            }
        }

        if (!first) __syncthreads();     // wsum safe from previous iteration
        first = false;
        if (lane == 31) {
            #pragma unroll
            for (int k = 0; k < NTILES; ++k)
                wsum[k * NWARPS + warp] = make_float2(is[k], iq[k]);
        }
        __syncthreads();

        // ---- single segmented cross-warp scan: 32 entries = 4 segs of 8 ----
        if (warp == 0) {
            float2 w = wsum[lane];
            float ws = w.x, wq = w.y;
            #pragma unroll
            for (int d = 1; d < NWARPS; d <<= 1) {
                float as = __shfl_up_sync(0xffffffffu, ws, d);
                float aq = __shfl_up_sync(0xffffffffu, wq, d);
                if ((lane & (NWARPS - 1)) >= d) { ws += as; wq += aq; }
            }
            wsum[lane] = make_float2(ws, wq);
        }
        __syncthreads();

        // ---- tail: normalize + store ----
        float* xo = out + (size_t)r * FRAMES;
        float cs = 0.f, cq = 0.f;
        #pragma unroll
        for (int k = 0; k < NTILES; ++k) {
            const float4 vk = v[k];
            const float ts = (vk.x + vk.y) + (vk.z + vk.w);
            float tq = vk.x * vk.x;
            tq = fmaf(vk.y, vk.y, tq);
            tq = fmaf(vk.z, vk.z, tq);
            tq = fmaf(vk.w, vk.w, tq);

            const float2 wp = (warp > 0) ? wsum[k * NWARPS + warp - 1]
                                         : make_float2(0.f, 0.f);
            float ps = cs + wp.x + (is[k] - ts);
            float pq = cq + wp.y + (iq[k] - tq);

            const float2 tot = wsum[k * NWARPS + (NWARPS - 1)];
            cs += tot.x;
            cq += tot.y;

            const int e = k * TILE + 4 * tid;
            if (k < NTILES - 1 || e < FRAMES) {
                float rr[4] = {vk.x, vk.y, vk.z, vk.w};
                float c = (float)e;
                #pragma unroll
                for (int j = 0; j < 4; ++j) {
                    const float xv = rr[j];
                    ps += xv;
                    pq  = fmaf(xv, xv, pq);
                    c  += 1.f;
                    const float ecc = (EPS * c) * c;
                    const float den = fmaf(c, pq, fmaf(-ps, ps, ecc)); // c*q - s^2 + eps*c^2
                    const float num = fmaf(c, xv, -ps);                // c*x - s
                    rr[j] = num * rsqrtf(den);
                }
                *reinterpret_cast<float4*>(xo + e) =
                    make_float4(rr[0], rr[1], rr[2], rr[3]);
            }
        }
    }
}

extern "C" void kernel_launch(void* const* d_in, const int* in_sizes, int n_in,
                              void* d_out, int out_size)
{
    const float* x = (const float*)d_in[0];
    float* outp    = (float*)d_out;
    const int rows = in_sizes[0] / FRAMES;      // 16384
    cumnorm_kernel<<<GRID, THREADS>>>(x, outp, rows);
}